// round 10
// baseline (speedup 1.0000x reference)
#include <cuda_runtime.h>

#define BB 4
#define TT 8
#define CC 64
#define FF 16
#define NN 8192   // T*H*W
#define HW 1024

typedef unsigned long long u64;

// Scratch: pooled transposed as float4 over batch, and sigmoid output v.
__device__ float4 g_p4[NN];        // g_p4[n] = (pooled[b=0..3][n])
__device__ float  g_v[BB * NN];    // v[b*N + n]

__device__ __forceinline__ u64 pack2(unsigned int w) {
    u64 r;
    asm("mov.b64 %0, {%1, %1};" : "=l"(r) : "r"(w));
    return r;
}
__device__ __forceinline__ void fma2(u64& acc, u64 a, u64 b) {
    asm("fma.rn.f32x2 %0, %1, %2, %0;" : "+l"(acc) : "l"(a), "l"(b));
}
__device__ __forceinline__ void unpack2(u64 v, float& lo, float& hi) {
    unsigned int l, h;
    asm("mov.b64 {%0, %1}, %2;" : "=r"(l), "=r"(h) : "l"(v));
    lo = __uint_as_float(l);
    hi = __uint_as_float(h);
}

// ---------------------------------------------------------------------------
// Kernel 1: pooled[b,n] = sum_c mean_f(conv1_w[f,c]) * x[b,t,c,hw] + mean_f(b)
// 16-way c-split, shuffle-tree combine. 1024 blocks x 128 threads.
// ---------------------------------------------------------------------------
__global__ __launch_bounds__(128) void k_pool(const float* __restrict__ x,
                                              const float* __restrict__ c1w,
                                              const float* __restrict__ c1b) {
    __shared__ float swb[CC];
    __shared__ float sbb;
    int tid = threadIdx.x;
    if (tid < CC) {
        float s = 0.f;
        #pragma unroll
        for (int f = 0; f < FF; f++) s += c1w[f * CC + tid];
        swb[tid] = s * (1.0f / FF);
    }
    if (tid == 0) {
        float s = 0.f;
        #pragma unroll
        for (int f = 0; f < FF; f++) s += c1b[f];
        sbb = s * (1.0f / FF);
    }
    __syncthreads();

    int s  = tid & 15;                // c-split (0..15), 4 channels each
    int q  = tid >> 4;                // quad within block (0..7)
    int G  = blockIdx.x * 8 + q;      // global quad id, 0..8191
    int b  = G >> 11;
    int nq = G & 2047;
    int n0 = nq * 4;
    int t  = n0 >> 10;
    int hw4 = (n0 & (HW - 1)) >> 2;

    const float4* xp = (const float4*)x
        + ((size_t)((b * TT + t) * CC + s * 4)) * (HW / 4) + hw4;

    float4 x0 = xp[0];
    float4 x1 = xp[HW / 4];
    float4 x2 = xp[2 * (HW / 4)];
    float4 x3 = xp[3 * (HW / 4)];
    float w0v = swb[s * 4 + 0], w1v = swb[s * 4 + 1];
    float w2v = swb[s * 4 + 2], w3v = swb[s * 4 + 3];

    float4 a;
    a.x = w0v * x0.x + w1v * x1.x + w2v * x2.x + w3v * x3.x;
    a.y = w0v * x0.y + w1v * x1.y + w2v * x2.y + w3v * x3.y;
    a.z = w0v * x0.z + w1v * x1.z + w2v * x2.z + w3v * x3.z;
    a.w = w0v * x0.w + w1v * x1.w + w2v * x2.w + w3v * x3.w;

    #pragma unroll
    for (int off = 1; off < 16; off <<= 1) {
        a.x += __shfl_xor_sync(0xffffffffu, a.x, off);
        a.y += __shfl_xor_sync(0xffffffffu, a.y, off);
        a.z += __shfl_xor_sync(0xffffffffu, a.z, off);
        a.w += __shfl_xor_sync(0xffffffffu, a.w, off);
    }
    if (s == 0) {
        float bb = sbb;
        float* gp = (float*)g_p4;
        gp[(n0 + 0) * 4 + b] = a.x + bb;
        gp[(n0 + 1) * 4 + b] = a.y + bb;
        gp[(n0 + 2) * 4 + b] = a.z + bb;
        gp[(n0 + 3) * 4 + b] = a.w + bb;
    }
}

// No-op launch to shift the ncu capture index (mod-4) onto k_gemv.
__global__ void k_nop() {}

// ---------------------------------------------------------------------------
// Kernel 2: v[b,n] = sigmoid( sum_m pooled[b,m] * W[n,m] + bias[n] )
// 128 CTAs x 512 threads, 128KB smem (pooled in 4 deinterleaved float4
// planes -> conflict-free LDS.128). Warp gw owns rows 4gw..4gw+3 for all 4
// batches; packed f32x2 accumulation. FOUR-stage W-prefetch pipeline: each
// stage's 4 LDG.128 issue 3 full compute stages before consumption -> 16
// LDG.128 (8KB) per warp outstanding, 128KB/SM in flight, covering loaded
// DRAM latency with margin. Smem operand read at consume time (29-cyc LDS
// hides itself). DRAM-bound by design.
// ---------------------------------------------------------------------------
__global__ __launch_bounds__(512) void k_gemv(const float* __restrict__ Wm,
                                              const float* __restrict__ bias) {
    extern __shared__ float4 sp[];   // sp[j*2048 + i] = g_p4[4*i + j], 128KB
    for (int idx = threadIdx.x; idx < NN; idx += 512)
        sp[(idx & 3) * 2048 + (idx >> 2)] = g_p4[idx];
    __syncthreads();

    int lane = threadIdx.x & 31;
    int gw   = blockIdx.x * 16 + (threadIdx.x >> 5);   // 0..2047, exact
    int n0 = gw * 4;
    const float4* w0 = (const float4*)Wm + (size_t)n0 * (NN / 4);
    const ulonglong2* spu = (const ulonglong2*)sp;     // .x=(b0,b1) .y=(b2,b3)

    u64 aL[4], aH[4];                // [row r]: L = batches 0,1; H = batches 2,3
    #pragma unroll
    for (int r = 0; r < 4; r++) { aL[r] = 0ull; aH[r] = 0ull; }

    float4 w[4][4];                  // [stage][row]

#define WLOAD(S, I)                                                           \
    {                                                                         \
        w[S][0] = __ldcs(w0 + (I));                                           \
        w[S][1] = __ldcs(w0 + 2048 + (I));                                    \
        w[S][2] = __ldcs(w0 + 4096 + (I));                                    \
        w[S][3] = __ldcs(w0 + 6144 + (I));                                    \
    }

#define STEP(S, I)                                                            \
    {                                                                         \
        ulonglong2 p0 = spu[(I)];                                             \
        ulonglong2 p1 = spu[2048 + (I)];                                      \
        ulonglong2 p2 = spu[4096 + (I)];                                      \
        ulonglong2 p3 = spu[6144 + (I)];                                      \
        _Pragma("unroll")                                                     \
        for (int r = 0; r < 4; r++) {                                         \
            u64 wx = pack2(__float_as_uint(w[S][r].x));                       \
            fma2(aL[r], wx, p0.x); fma2(aH[r], wx, p0.y);                     \
            u64 wy = pack2(__float_as_uint(w[S][r].y));                       \
            fma2(aL[r], wy, p1.x); fma2(aH[r], wy, p1.y);                     \
            u64 wz = pack2(__float_as_uint(w[S][r].z));                       \
            fma2(aL[r], wz, p2.x); fma2(aH[r], wz, p2.y);                     \
            u64 ww = pack2(__float_as_uint(w[S][r].w));                       \
            fma2(aL[r], ww, p3.x); fma2(aH[r], ww, p3.y);                     \
        }                                                                     \
    }

    // Prologue: fill 4 stages.
    WLOAD(0, lane);
    WLOAD(1, lane + 32);
    WLOAD(2, lane + 64);
    WLOAD(3, lane + 96);

    int base = lane;
    // 64 trips total; 15 main blocks of 4 trips (with refills) + epilogue.
    #pragma unroll 1
    for (int blk = 0; blk < 15; blk++) {
        STEP(0, base);        WLOAD(0, base + 128);
        STEP(1, base + 32);   WLOAD(1, base + 160);
        STEP(2, base + 64);   WLOAD(2, base + 192);
        STEP(3, base + 96);   WLOAD(3, base + 224);
        base += 128;
    }
    STEP(0, base);
    STEP(1, base + 32);
    STEP(2, base + 64);
    STEP(3, base + 96);
#undef WLOAD
#undef STEP

    float acc[16];
    #pragma unroll
    for (int r = 0; r < 4; r++) {
        unpack2(aL[r], acc[r * 4 + 0], acc[r * 4 + 1]);
        unpack2(aH[r], acc[r * 4 + 2], acc[r * 4 + 3]);
    }
    #pragma unroll
    for (int k = 0; k < 16; k++)
        #pragma unroll
        for (int off = 16; off > 0; off >>= 1)
            acc[k] += __shfl_xor_sync(0xffffffffu, acc[k], off);

    if (lane < 16) {
        int r = lane >> 2, b = lane & 3;
        float z = acc[lane] + bias[n0 + r];
        g_v[b * NN + n0 + r] = 1.0f / (1.0f + __expf(-z));
    }
}

// ---------------------------------------------------------------------------
// Kernel 3: out[b,t,f,h,w] = v[b,n] * (sum_c g3_w[f,c]*x[b,t,c,hw] + g3_b[f])
// 256 blocks x 128 threads, 16 f-accumulators, weights in SMEM.
// ---------------------------------------------------------------------------
__global__ __launch_bounds__(128) void k_out(const float* __restrict__ x,
                                             const float* __restrict__ g3w,
                                             const float* __restrict__ g3b,
                                             float* __restrict__ out) {
    __shared__ float sw[FF * CC];
    __shared__ float sb[FF];
    for (int idx = threadIdx.x; idx < FF * CC; idx += 128) sw[idx] = g3w[idx];
    if (threadIdx.x < FF) sb[threadIdx.x] = g3b[threadIdx.x];
    __syncthreads();

    int g  = blockIdx.x * 128 + threadIdx.x;
    int b  = g >> 13;
    int n  = g & (NN - 1);
    int t  = n >> 10;
    int hw = n & (HW - 1);
    const float* xp = x + (size_t)((b * TT + t) * CC) * HW + hw;

    float acc[FF];
    #pragma unroll
    for (int f = 0; f < FF; f++) acc[f] = sb[f];

    #pragma unroll 8
    for (int c = 0; c < CC; c++) {
        float xv = xp[c * HW];
        #pragma unroll
        for (int f = 0; f < FF; f++) acc[f] += sw[f * CC + c] * xv;
    }

    float v = g_v[b * NN + n];
    float* op = out + (size_t)((b * TT + t) * FF) * HW + hw;
    #pragma unroll
    for (int f = 0; f < FF; f++) op[f * HW] = v * acc[f];
}

extern "C" void kernel_launch(void* const* d_in, const int* in_sizes, int n_in,
                              void* d_out, int out_size) {
    const float* x   = (const float*)d_in[0];
    // d_in[1] = x1, unused by the reference forward
    const float* c1w = (const float*)d_in[2];
    const float* c1b = (const float*)d_in[3];
    const float* g3w = (const float*)d_in[4];
    const float* g3b = (const float*)d_in[5];
    const float* fw  = (const float*)d_in[6];
    const float* fb  = (const float*)d_in[7];
    float* out = (float*)d_out;

    cudaFuncSetAttribute(k_gemv, cudaFuncAttributeMaxDynamicSharedMemorySize, 131072);

    k_pool<<<1024, 128>>>(x, c1w, c1b);
    k_nop<<<1, 32>>>();                            // shifts ncu capture onto k_gemv
    k_gemv<<<128, 512, 131072>>>(fw, fb);          // 128*16 warps = 2048 tasks, exact
    k_out<<<(BB * NN) / 128, 128>>>(x, g3w, g3b, out);
}

// round 15
// speedup vs baseline: 1.1493x; 1.1493x over previous
#include <cuda_runtime.h>

#define BB 4
#define TT 8
#define CC 64
#define FF 16
#define NN 8192   // T*H*W
#define HW 1024

typedef unsigned long long u64;

// Scratch: pooled transposed as float4 over batch, and sigmoid output v.
__device__ float4 g_p4[NN];        // g_p4[n] = (pooled[b=0..3][n])
__device__ float  g_v[BB * NN];    // v[b*N + n]

__device__ __forceinline__ u64 pack2(unsigned int w) {
    u64 r;
    asm("mov.b64 %0, {%1, %1};" : "=l"(r) : "r"(w));
    return r;
}
__device__ __forceinline__ void fma2(u64& acc, u64 a, u64 b) {
    asm("fma.rn.f32x2 %0, %1, %2, %0;" : "+l"(acc) : "l"(a), "l"(b));
}
__device__ __forceinline__ void unpack2(u64 v, float& lo, float& hi) {
    unsigned int l, h;
    asm("mov.b64 {%0, %1}, %2;" : "=r"(l), "=r"(h) : "l"(v));
    lo = __uint_as_float(l);
    hi = __uint_as_float(h);
}

// ---------------------------------------------------------------------------
// Kernel 1: pooled[b,n] = sum_c mean_f(conv1_w[f,c]) * x[b,t,c,hw] + mean_f(b)
// 16-way c-split, shuffle-tree combine. 1024 blocks x 128 threads.
// ---------------------------------------------------------------------------
__global__ __launch_bounds__(128) void k_pool(const float* __restrict__ x,
                                              const float* __restrict__ c1w,
                                              const float* __restrict__ c1b) {
    __shared__ float swb[CC];
    __shared__ float sbb;
    int tid = threadIdx.x;
    if (tid < CC) {
        float s = 0.f;
        #pragma unroll
        for (int f = 0; f < FF; f++) s += c1w[f * CC + tid];
        swb[tid] = s * (1.0f / FF);
    }
    if (tid == 0) {
        float s = 0.f;
        #pragma unroll
        for (int f = 0; f < FF; f++) s += c1b[f];
        sbb = s * (1.0f / FF);
    }
    __syncthreads();

    int s  = tid & 15;                // c-split (0..15), 4 channels each
    int q  = tid >> 4;                // quad within block (0..7)
    int G  = blockIdx.x * 8 + q;      // global quad id, 0..8191
    int b  = G >> 11;
    int nq = G & 2047;
    int n0 = nq * 4;
    int t  = n0 >> 10;
    int hw4 = (n0 & (HW - 1)) >> 2;

    const float4* xp = (const float4*)x
        + ((size_t)((b * TT + t) * CC + s * 4)) * (HW / 4) + hw4;

    float4 x0 = xp[0];
    float4 x1 = xp[HW / 4];
    float4 x2 = xp[2 * (HW / 4)];
    float4 x3 = xp[3 * (HW / 4)];
    float w0v = swb[s * 4 + 0], w1v = swb[s * 4 + 1];
    float w2v = swb[s * 4 + 2], w3v = swb[s * 4 + 3];

    float4 a;
    a.x = w0v * x0.x + w1v * x1.x + w2v * x2.x + w3v * x3.x;
    a.y = w0v * x0.y + w1v * x1.y + w2v * x2.y + w3v * x3.y;
    a.z = w0v * x0.z + w1v * x1.z + w2v * x2.z + w3v * x3.z;
    a.w = w0v * x0.w + w1v * x1.w + w2v * x2.w + w3v * x3.w;

    #pragma unroll
    for (int off = 1; off < 16; off <<= 1) {
        a.x += __shfl_xor_sync(0xffffffffu, a.x, off);
        a.y += __shfl_xor_sync(0xffffffffu, a.y, off);
        a.z += __shfl_xor_sync(0xffffffffu, a.z, off);
        a.w += __shfl_xor_sync(0xffffffffu, a.w, off);
    }
    if (s == 0) {
        float bb = sbb;
        float* gp = (float*)g_p4;
        gp[(n0 + 0) * 4 + b] = a.x + bb;
        gp[(n0 + 1) * 4 + b] = a.y + bb;
        gp[(n0 + 2) * 4 + b] = a.z + bb;
        gp[(n0 + 3) * 4 + b] = a.w + bb;
    }
}

// ---------------------------------------------------------------------------
// Kernel 2: v[b,n] = sigmoid( sum_m pooled[b,m] * W[n,m] + bias[n] )
// 128 CTAs x 512 threads, 128KB smem (pooled in 4 deinterleaved float4
// planes). THREE-stage W-prefetch pipeline: 12 LDG.128/warp outstanding
// (96KB/SM) while staying inside the 6 scoreboard slots and ~90 regs
// (the 4-stage variant regressed on exactly those limits). Smem operand
// read at consume time. Packed f32x2 accumulation.
// ---------------------------------------------------------------------------
__global__ __launch_bounds__(512) void k_gemv(const float* __restrict__ Wm,
                                              const float* __restrict__ bias) {
    extern __shared__ float4 sp[];   // sp[j*2048 + i] = g_p4[4*i + j], 128KB
    for (int idx = threadIdx.x; idx < NN; idx += 512)
        sp[(idx & 3) * 2048 + (idx >> 2)] = g_p4[idx];
    __syncthreads();

    int lane = threadIdx.x & 31;
    int gw   = blockIdx.x * 16 + (threadIdx.x >> 5);   // 0..2047, exact
    int n0 = gw * 4;
    const float4* w0 = (const float4*)Wm + (size_t)n0 * (NN / 4);
    const ulonglong2* spu = (const ulonglong2*)sp;     // .x=(b0,b1) .y=(b2,b3)

    u64 aL[4], aH[4];                // [row r]: L = batches 0,1; H = batches 2,3
    #pragma unroll
    for (int r = 0; r < 4; r++) { aL[r] = 0ull; aH[r] = 0ull; }

    float4 w[3][4];                  // [stage][row]

#define WLOAD(S, I)                                                           \
    {                                                                         \
        w[S][0] = __ldcs(w0 + (I));                                           \
        w[S][1] = __ldcs(w0 + 2048 + (I));                                    \
        w[S][2] = __ldcs(w0 + 4096 + (I));                                    \
        w[S][3] = __ldcs(w0 + 6144 + (I));                                    \
    }

#define STEP(S, I)                                                            \
    {                                                                         \
        ulonglong2 p0 = spu[(I)];                                             \
        ulonglong2 p1 = spu[2048 + (I)];                                      \
        ulonglong2 p2 = spu[4096 + (I)];                                      \
        ulonglong2 p3 = spu[6144 + (I)];                                      \
        _Pragma("unroll")                                                     \
        for (int r = 0; r < 4; r++) {                                         \
            u64 wx = pack2(__float_as_uint(w[S][r].x));                       \
            fma2(aL[r], wx, p0.x); fma2(aH[r], wx, p0.y);                     \
            u64 wy = pack2(__float_as_uint(w[S][r].y));                       \
            fma2(aL[r], wy, p1.x); fma2(aH[r], wy, p1.y);                     \
            u64 wz = pack2(__float_as_uint(w[S][r].z));                       \
            fma2(aL[r], wz, p2.x); fma2(aH[r], wz, p2.y);                     \
            u64 ww = pack2(__float_as_uint(w[S][r].w));                       \
            fma2(aL[r], ww, p3.x); fma2(aH[r], ww, p3.y);                     \
        }                                                                     \
    }

    // Prologue: fill 3 stages (trips at lane, lane+32, lane+64).
    WLOAD(0, lane);
    WLOAD(1, lane + 32);
    WLOAD(2, lane + 64);

    // 64 trips total = 3*20 + 4.
    int base = lane;
    #pragma unroll 1
    for (int blk = 0; blk < 20; blk++) {
        STEP(0, base);        WLOAD(0, base + 96);
        STEP(1, base + 32);   WLOAD(1, base + 128);
        STEP(2, base + 64);   WLOAD(2, base + 160);
        base += 96;
    }
    // base = lane + 1920; stages hold trips 1920/1952/1984; one trip (2016) left.
    STEP(0, base);            WLOAD(0, base + 96);     // load trip 2016
    STEP(1, base + 32);
    STEP(2, base + 64);
    STEP(0, base + 96);
#undef WLOAD
#undef STEP

    float acc[16];
    #pragma unroll
    for (int r = 0; r < 4; r++) {
        unpack2(aL[r], acc[r * 4 + 0], acc[r * 4 + 1]);
        unpack2(aH[r], acc[r * 4 + 2], acc[r * 4 + 3]);
    }
    #pragma unroll
    for (int k = 0; k < 16; k++)
        #pragma unroll
        for (int off = 16; off > 0; off >>= 1)
            acc[k] += __shfl_xor_sync(0xffffffffu, acc[k], off);

    if (lane < 16) {
        int r = lane >> 2, b = lane & 3;
        float z = acc[lane] + bias[n0 + r];
        g_v[b * NN + n0 + r] = 1.0f / (1.0f + __expf(-z));
    }
}

// ---------------------------------------------------------------------------
// Kernel 3: out[b,t,f,h,w] = v[b,n] * (sum_c g3_w[f,c]*x[b,t,c,hw] + g3_b[f])
// 256 blocks x 256 threads; each block covers 128 outputs, each output is
// handled by a thread PAIR splitting the c-reduction (32 c each, 65K threads
// total -> half-length latency chains, 2x warps/SM), combined through smem.
// ---------------------------------------------------------------------------
__global__ __launch_bounds__(256) void k_out(const float* __restrict__ x,
                                             const float* __restrict__ g3w,
                                             const float* __restrict__ g3b,
                                             float* __restrict__ out) {
    __shared__ float sw[FF * CC];
    __shared__ float red[128 * FF];   // 8KB partials from the upper half
    int tid = threadIdx.x;
    for (int idx = tid; idx < FF * CC; idx += 256) sw[idx] = g3w[idx];
    __syncthreads();

    int o    = tid & 127;             // output slot within block
    int half = tid >> 7;              // c-half (0/1)
    int g    = blockIdx.x * 128 + o;  // 0..32767 (256 blocks * 128 outputs)
    int b    = g >> 13;
    int n    = g & (NN - 1);
    int t    = n >> 10;
    int hw   = n & (HW - 1);
    const float* xp = x + (size_t)((b * TT + t) * CC + half * 32) * HW + hw;

    float acc[FF];
    #pragma unroll
    for (int f = 0; f < FF; f++) acc[f] = 0.f;

    #pragma unroll 8
    for (int c = 0; c < 32; c++) {
        float xv = xp[c * HW];
        #pragma unroll
        for (int f = 0; f < FF; f++) acc[f] += sw[f * CC + half * 32 + c] * xv;
    }

    if (half == 1) {
        #pragma unroll
        for (int f = 0; f < FF; f++) red[o * FF + f] = acc[f];
    }
    __syncthreads();
    if (half == 0) {
        float v = g_v[b * NN + n];
        float* op = out + (size_t)((b * TT + t) * FF) * HW + hw;
        #pragma unroll
        for (int f = 0; f < FF; f++)
            op[f * HW] = v * (acc[f] + red[o * FF + f] + g3b[f]);
    }
}

extern "C" void kernel_launch(void* const* d_in, const int* in_sizes, int n_in,
                              void* d_out, int out_size) {
    const float* x   = (const float*)d_in[0];
    // d_in[1] = x1, unused by the reference forward
    const float* c1w = (const float*)d_in[2];
    const float* c1b = (const float*)d_in[3];
    const float* g3w = (const float*)d_in[4];
    const float* g3b = (const float*)d_in[5];
    const float* fw  = (const float*)d_in[6];
    const float* fb  = (const float*)d_in[7];
    float* out = (float*)d_out;

    cudaFuncSetAttribute(k_gemv, cudaFuncAttributeMaxDynamicSharedMemorySize, 131072);

    k_pool<<<1024, 128>>>(x, c1w, c1b);
    k_gemv<<<128, 512, 131072>>>(fw, fb);          // 128*16 warps = 2048 tasks, exact
    k_out<<<256, 256>>>(x, g3w, g3b, out);         // 256*128 = 32768 outputs, exact
}

// round 17
// speedup vs baseline: 1.3134x; 1.1428x over previous
#include <cuda_runtime.h>

#define BB 4
#define TT 8
#define CC 64
#define FF 16
#define NN 8192   // T*H*W
#define HW 1024

typedef unsigned long long u64;

// Scratch: pooled transposed as float4 over batch; K-half partial z sums.
__device__ float4 g_p4[NN];          // g_p4[n] = (pooled[b=0..3][n])
__device__ float  g_zp[2][BB * NN];  // partial z per k-half (bias folded in half 0)

__device__ __forceinline__ u64 pack2(unsigned int w) {
    u64 r;
    asm("mov.b64 %0, {%1, %1};" : "=l"(r) : "r"(w));
    return r;
}
__device__ __forceinline__ void fma2(u64& acc, u64 a, u64 b) {
    asm("fma.rn.f32x2 %0, %1, %2, %0;" : "+l"(acc) : "l"(a), "l"(b));
}
__device__ __forceinline__ void unpack2(u64 v, float& lo, float& hi) {
    unsigned int l, h;
    asm("mov.b64 {%0, %1}, %2;" : "=r"(l), "=r"(h) : "l"(v));
    lo = __uint_as_float(l);
    hi = __uint_as_float(h);
}

// ---------------------------------------------------------------------------
// Kernel 1: pooled[b,n] = sum_c mean_f(conv1_w[f,c]) * x[b,t,c,hw] + mean_f(b)
// 16-way c-split, shuffle-tree combine. 1024 blocks x 128 threads.
// ---------------------------------------------------------------------------
__global__ __launch_bounds__(128) void k_pool(const float* __restrict__ x,
                                              const float* __restrict__ c1w,
                                              const float* __restrict__ c1b) {
    __shared__ float swb[CC];
    __shared__ float sbb;
    int tid = threadIdx.x;
    if (tid < CC) {
        float s = 0.f;
        #pragma unroll
        for (int f = 0; f < FF; f++) s += c1w[f * CC + tid];
        swb[tid] = s * (1.0f / FF);
    }
    if (tid == 0) {
        float s = 0.f;
        #pragma unroll
        for (int f = 0; f < FF; f++) s += c1b[f];
        sbb = s * (1.0f / FF);
    }
    __syncthreads();

    int s  = tid & 15;                // c-split (0..15), 4 channels each
    int q  = tid >> 4;                // quad within block (0..7)
    int G  = blockIdx.x * 8 + q;      // global quad id, 0..8191
    int b  = G >> 11;
    int nq = G & 2047;
    int n0 = nq * 4;
    int t  = n0 >> 10;
    int hw4 = (n0 & (HW - 1)) >> 2;

    const float4* xp = (const float4*)x
        + ((size_t)((b * TT + t) * CC + s * 4)) * (HW / 4) + hw4;

    float4 x0 = xp[0];
    float4 x1 = xp[HW / 4];
    float4 x2 = xp[2 * (HW / 4)];
    float4 x3 = xp[3 * (HW / 4)];
    float w0v = swb[s * 4 + 0], w1v = swb[s * 4 + 1];
    float w2v = swb[s * 4 + 2], w3v = swb[s * 4 + 3];

    float4 a;
    a.x = w0v * x0.x + w1v * x1.x + w2v * x2.x + w3v * x3.x;
    a.y = w0v * x0.y + w1v * x1.y + w2v * x2.y + w3v * x3.y;
    a.z = w0v * x0.z + w1v * x1.z + w2v * x2.z + w3v * x3.z;
    a.w = w0v * x0.w + w1v * x1.w + w2v * x2.w + w3v * x3.w;

    #pragma unroll
    for (int off = 1; off < 16; off <<= 1) {
        a.x += __shfl_xor_sync(0xffffffffu, a.x, off);
        a.y += __shfl_xor_sync(0xffffffffu, a.y, off);
        a.z += __shfl_xor_sync(0xffffffffu, a.z, off);
        a.w += __shfl_xor_sync(0xffffffffu, a.w, off);
    }
    if (s == 0) {
        float bb = sbb;
        float* gp = (float*)g_p4;
        gp[(n0 + 0) * 4 + b] = a.x + bb;
        gp[(n0 + 1) * 4 + b] = a.y + bb;
        gp[(n0 + 2) * 4 + b] = a.z + bb;
        gp[(n0 + 3) * 4 + b] = a.w + bb;
    }
}

// ---------------------------------------------------------------------------
// Kernel 2: partial z[kh][b,n] = sum_{m in half kh} pooled[b,m] * W[n,m]
// Grid 296 = 2 CTAs/SM x 148 SMs. Each CTA owns ONE K-half: 64KB smem of
// pooled-half (4 deinterleaved planes). 14 warps x 448 thr, <=72 regs via
// launch_bounds(448,2) so both CTAs co-reside -> 28 warps/SM, ~2x chip
// in-flight LDG bytes vs the 16-warp/1-CTA version (the measured binder).
// Static task map: warp (bid>>1)*14+w handles rows 4t..4t+3 over its half.
// 2-stage W prefetch; packed f32x2 accumulation.
// ---------------------------------------------------------------------------
__global__ __launch_bounds__(448, 2) void k_gemv(const float* __restrict__ Wm,
                                                 const float* __restrict__ bias) {
    extern __shared__ float4 sp[];   // 4 planes x 1024 float4 = 64KB (one K-half)
    int kh = blockIdx.x & 1;
    for (int idx = threadIdx.x; idx < NN / 2; idx += 448)
        sp[(idx & 3) * 1024 + (idx >> 2)] = g_p4[kh * (NN / 2) + idx];
    __syncthreads();

    int lane = threadIdx.x & 31;
    int task = (blockIdx.x >> 1) * 14 + (threadIdx.x >> 5);   // 0..2071
    if (task >= NN / 4) return;                               // 24 idle warps/half
    int n0 = task * 4;
    const float4* w0 = (const float4*)Wm + (size_t)n0 * (NN / 4) + kh * 1024;
    const ulonglong2* spu = (const ulonglong2*)sp;            // planes at 0/1024/2048/3072

    u64 aL[4], aH[4];
    #pragma unroll
    for (int r = 0; r < 4; r++) { aL[r] = 0ull; aH[r] = 0ull; }

    float4 w[2][4];                  // [stage][row]

#define WLOAD(S, I)                                                           \
    {                                                                         \
        w[S][0] = __ldcs(w0 + (I));                                           \
        w[S][1] = __ldcs(w0 + 2048 + (I));                                    \
        w[S][2] = __ldcs(w0 + 4096 + (I));                                    \
        w[S][3] = __ldcs(w0 + 6144 + (I));                                    \
    }

#define STEP(S, I)                                                            \
    {                                                                         \
        ulonglong2 p0 = spu[(I)];                                             \
        ulonglong2 p1 = spu[1024 + (I)];                                      \
        ulonglong2 p2 = spu[2048 + (I)];                                      \
        ulonglong2 p3 = spu[3072 + (I)];                                      \
        _Pragma("unroll")                                                     \
        for (int r = 0; r < 4; r++) {                                         \
            u64 wx = pack2(__float_as_uint(w[S][r].x));                       \
            fma2(aL[r], wx, p0.x); fma2(aH[r], wx, p0.y);                     \
            u64 wy = pack2(__float_as_uint(w[S][r].y));                       \
            fma2(aL[r], wy, p1.x); fma2(aH[r], wy, p1.y);                     \
            u64 wz = pack2(__float_as_uint(w[S][r].z));                       \
            fma2(aL[r], wz, p2.x); fma2(aH[r], wz, p2.y);                     \
            u64 ww = pack2(__float_as_uint(w[S][r].w));                       \
            fma2(aL[r], ww, p3.x); fma2(aH[r], ww, p3.y);                     \
        }                                                                     \
    }

    // 32 trips over this K-half (1024 float4 per row / 32 lanes).
    WLOAD(0, lane);
    WLOAD(1, lane + 32);
    int base = lane;
    #pragma unroll 1
    for (int blk = 0; blk < 15; blk++) {
        STEP(0, base);        WLOAD(0, base + 64);
        STEP(1, base + 32);   WLOAD(1, base + 96);
        base += 64;
    }
    STEP(0, base);
    STEP(1, base + 32);
#undef WLOAD
#undef STEP

    float acc[16];
    #pragma unroll
    for (int r = 0; r < 4; r++) {
        unpack2(aL[r], acc[r * 4 + 0], acc[r * 4 + 1]);
        unpack2(aH[r], acc[r * 4 + 2], acc[r * 4 + 3]);
    }
    #pragma unroll
    for (int k = 0; k < 16; k++)
        #pragma unroll
        for (int off = 16; off > 0; off >>= 1)
            acc[k] += __shfl_xor_sync(0xffffffffu, acc[k], off);

    if (lane < 16) {
        int r = lane >> 2, b = lane & 3;
        float z = acc[lane] + (kh == 0 ? bias[n0 + r] : 0.f);
        g_zp[kh][b * NN + n0 + r] = z;
    }
}

// ---------------------------------------------------------------------------
// Kernel 3: out[b,t,f,h,w] = v[b,n] * (sum_c g3_w[f,c]*x[b,t,c,hw] + g3_b[f])
// with v = sigmoid(zp0 + zp1) fused here. 256 blocks x 256 threads; thread
// PAIRS split the c-reduction, combined through smem.
// ---------------------------------------------------------------------------
__global__ __launch_bounds__(256) void k_out(const float* __restrict__ x,
                                             const float* __restrict__ g3w,
                                             const float* __restrict__ g3b,
                                             float* __restrict__ out) {
    __shared__ float sw[FF * CC];
    __shared__ float red[128 * FF];   // 8KB partials from the upper half
    int tid = threadIdx.x;
    for (int idx = tid; idx < FF * CC; idx += 256) sw[idx] = g3w[idx];
    __syncthreads();

    int o    = tid & 127;             // output slot within block
    int half = tid >> 7;              // c-half (0/1)
    int g    = blockIdx.x * 128 + o;  // 0..32767 (256 blocks * 128 outputs)
    int b    = g >> 13;
    int n    = g & (NN - 1);
    int t    = n >> 10;
    int hw   = n & (HW - 1);
    const float* xp = x + (size_t)((b * TT + t) * CC + half * 32) * HW + hw;

    float acc[FF];
    #pragma unroll
    for (int f = 0; f < FF; f++) acc[f] = 0.f;

    #pragma unroll 8
    for (int c = 0; c < 32; c++) {
        float xv = xp[c * HW];
        #pragma unroll
        for (int f = 0; f < FF; f++) acc[f] += sw[f * CC + half * 32 + c] * xv;
    }

    if (half == 1) {
        #pragma unroll
        for (int f = 0; f < FF; f++) red[o * FF + f] = acc[f];
    }
    __syncthreads();
    if (half == 0) {
        float z = g_zp[0][b * NN + n] + g_zp[1][b * NN + n];
        float v = 1.0f / (1.0f + __expf(-z));
        float* op = out + (size_t)((b * TT + t) * FF) * HW + hw;
        #pragma unroll
        for (int f = 0; f < FF; f++)
            op[f * HW] = v * (acc[f] + red[o * FF + f] + g3b[f]);
    }
}

extern "C" void kernel_launch(void* const* d_in, const int* in_sizes, int n_in,
                              void* d_out, int out_size) {
    const float* x   = (const float*)d_in[0];
    // d_in[1] = x1, unused by the reference forward
    const float* c1w = (const float*)d_in[2];
    const float* c1b = (const float*)d_in[3];
    const float* g3w = (const float*)d_in[4];
    const float* g3b = (const float*)d_in[5];
    const float* fw  = (const float*)d_in[6];
    const float* fb  = (const float*)d_in[7];
    float* out = (float*)d_out;

    cudaFuncSetAttribute(k_gemv, cudaFuncAttributeMaxDynamicSharedMemorySize, 65536);

    k_pool<<<1024, 128>>>(x, c1w, c1b);
    k_gemv<<<296, 448, 65536>>>(fw, fb);   // 2 CTAs/SM x 148 SMs, K-half each
    k_out<<<256, 256>>>(x, g3w, g3b, out); // 256*128 = 32768 outputs, exact
}